// round 17
// baseline (speedup 1.0000x reference)
#include <cuda_runtime.h>

#define IN_CH 16
#define OUT_CH 64
#define HDIM 32
#define WDIM 32
#define NB 8
#define KHW 9
#define F (IN_CH * KHW)      // 144
#define OCG 8                // out channels per block
#define ROWS 2               // output rows per block
#define NQ 8                 // column quads (4 cols per thread)
#define TPB 256              // 8q * 2r * 2os * 8cs
#define TW 36                // tile width (16B-aligned rows; cols 0..33 valid)
#define PSP 20               // ps inner stride (floats) -> conflict-free 128b ops

__global__ __launch_bounds__(TPB, 6) void normdist_kernel(
    const float* __restrict__ x,      // (8,16,32,32)
    const float* __restrict__ weight, // (64,144)
    const float* __restrict__ bias,   // (64)
    float* __restrict__ out)          // (8,64,32,32)
{
    const int og  = blockIdx.x;            // 0..7 out-channel group
    const int rg  = blockIdx.y;            // 0..15 row group
    const int n   = blockIdx.z;            // 0..7 batch
    const int tid = threadIdx.x;
    const int q   = tid & 7;               // 0..7 column quad (cols 4q..4q+3)
    const int r   = (tid >> 3) & 1;        // 0..1 row
    const int os  = (tid >> 4) & 1;        // 0..1 oc half (4 ocs)
    const int cs  = tid >> 5;              // 0..7 channel pair (warp-uniform)

    const int row0 = rg * ROWS;

    __shared__ __align__(16) float xs[IN_CH * (ROWS + 2) * TW];  // 9216 B
    __shared__ __align__(16) float wT[F * OCG];                  // 4608 B
    __shared__ __align__(16) float ps[7][ROWS][NQ][2][PSP];      // 22400 B

    // ---- transposed weights: wT[f*8+oo] = weight[(og*8+oo)*144 + f]
    {
        const float* wsrc = weight + og * OCG * F;
        #pragma unroll
        for (int k = 0; k < 5; k++) {
            int idx = tid + k * TPB;
            if (idx < F * OCG) {
                int oo = idx & 7;
                int f  = idx >> 3;
                wT[f * OCG + oo] = wsrc[oo * F + f];
            }
        }
    }

    // ---- x tile with halo; shift-only indexing (64 (c,rr) pairs x 4 lanes)
    {
        const float* xn = x + (size_t)n * IN_CH * HDIM * WDIM;
        const int pair = tid >> 2;             // 0..63
        const int l4   = tid & 3;
        const int c    = pair >> 2;            // 0..15
        const int rr   = pair & 3;             // 0..3
        const int gr   = row0 - 1 + rr;
        const bool rok = (gr >= 0) && (gr < HDIM);
        const float* src = xn + (c * HDIM + gr) * WDIM;
        float* dst = &xs[(c * (ROWS + 2) + rr) * TW];
        #pragma unroll
        for (int e = 0; e < 9; e++) {          // 9*4 = 36 >= 34
            int cc = l4 + e * 4;
            if (cc < 34) {
                int gc = cc - 1;
                float v = 0.0f;
                if (rok && gc >= 0 && gc < WDIM) v = src[gc];
                dst[cc] = v;
            }
        }
    }
    __syncthreads();

    // 4 columns x 4 out-channels of accumulators
    float acc[4][4];
    #pragma unroll
    for (int k = 0; k < 4; k++)
        #pragma unroll
        for (int o = 0; o < 4; o++) acc[k][o] = 0.0f;

    const int c0 = cs * 2;
    const float* x0 = &xs[(c0 * (ROWS + 2) + r) * TW + 4 * q];
    const float* x1 = x0 + (ROWS + 2) * TW;          // channel c0+1
    const float* wb0 = &wT[(c0 * KHW) * OCG + os * 4];
    const float* wb1 = wb0 + KHW * OCG;

    #pragma unroll
    for (int i = 0; i < 3; i++) {
        // 6-wide patch rows, both channels: LDS.128 + LDS.64 each (16B-aligned)
        float p0[6], p1[6];
        {
            float4 a4 = *reinterpret_cast<const float4*>(x0 + i * TW);
            float2 a2 = *reinterpret_cast<const float2*>(x0 + i * TW + 4);
            p0[0] = a4.x; p0[1] = a4.y; p0[2] = a4.z; p0[3] = a4.w;
            p0[4] = a2.x; p0[5] = a2.y;
            float4 b4 = *reinterpret_cast<const float4*>(x1 + i * TW);
            float2 b2 = *reinterpret_cast<const float2*>(x1 + i * TW + 4);
            p1[0] = b4.x; p1[1] = b4.y; p1[2] = b4.z; p1[3] = b4.w;
            p1[4] = b2.x; p1[5] = b2.y;
        }

        #pragma unroll
        for (int j = 0; j < 3; j++) {
            float4 w0 = *reinterpret_cast<const float4*>(wb0 + (i * 3 + j) * OCG);
            float4 w1 = *reinterpret_cast<const float4*>(wb1 + (i * 3 + j) * OCG);
            #pragma unroll
            for (int k = 0; k < 4; k++) {
                const float pa = p0[j + k];
                const float pb = p1[j + k];
                acc[k][0] = fmaxf(fmaxf(acc[k][0], fabsf(pa - w0.x)), fabsf(pb - w1.x));
                acc[k][1] = fmaxf(fmaxf(acc[k][1], fabsf(pa - w0.y)), fabsf(pb - w1.y));
                acc[k][2] = fmaxf(fmaxf(acc[k][2], fabsf(pa - w0.z)), fabsf(pb - w1.z));
                acc[k][3] = fmaxf(fmaxf(acc[k][3], fabsf(pa - w0.w)), fabsf(pb - w1.w));
            }
        }
    }

    // ---- reduce the 8 channel-pairs (single stage)
    if (cs > 0) {
        float* p = &ps[cs - 1][r][q][os][0];
        #pragma unroll
        for (int k = 0; k < 4; k++)
            *reinterpret_cast<float4*>(p + k * 4) =
                make_float4(acc[k][0], acc[k][1], acc[k][2], acc[k][3]);
    }
    __syncthreads();

    if (cs == 0) {
        #pragma unroll
        for (int g = 0; g < 7; g++) {
            const float* p = &ps[g][r][q][os][0];
            #pragma unroll
            for (int k = 0; k < 4; k++) {
                float4 v = *reinterpret_cast<const float4*>(p + k * 4);
                acc[k][0] = fmaxf(acc[k][0], v.x);
                acc[k][1] = fmaxf(acc[k][1], v.y);
                acc[k][2] = fmaxf(acc[k][2], v.z);
                acc[k][3] = fmaxf(acc[k][3], v.w);
            }
        }

        const int orow = row0 + r;
        float* outp = out + (((size_t)n * OUT_CH + og * OCG + os * 4) * HDIM + orow) * WDIM
                    + 4 * q;
        #pragma unroll
        for (int o = 0; o < 4; o++) {
            const float bi = __ldg(&bias[og * OCG + os * 4 + o]);
            float4 res = make_float4(acc[0][o] + bi, acc[1][o] + bi,
                                     acc[2][o] + bi, acc[3][o] + bi);
            *reinterpret_cast<float4*>(outp + (size_t)o * HDIM * WDIM) = res;
        }
    }
}

extern "C" void kernel_launch(void* const* d_in, const int* in_sizes, int n_in,
                              void* d_out, int out_size) {
    const float* x      = (const float*)d_in[0];
    const float* weight = (const float*)d_in[1];
    const float* bias   = (const float*)d_in[2];
    float* out          = (float*)d_out;

    dim3 grid(OUT_CH / OCG, HDIM / ROWS, NB);   // (8, 16, 8) = 1024 blocks
    normdist_kernel<<<grid, TPB>>>(x, weight, bias, out);
}